// round 1
// baseline (speedup 1.0000x reference)
#include <cuda_runtime.h>
#include <math.h>

#define Hdim 512
#define Wdim 512
#define Kdim 8
#define HW   (Hdim*Wdim)          // 262144
#define KHW  ((size_t)Kdim*HW)    // 2097152

// ---------------- scratch (device globals; no runtime allocation) ----------
__device__ float g_fm  [KHW*64];   // [K,H,W,64] : ch 0..31 = MLP feat, 32..63 = color feat
__device__ float g_tmp [KHW*64];   // generic intermediate
__device__ float g_m   [KHW*64];   // mpn2 raw logits
__device__ float g_ck  [KHW*3];    // colors transposed to [K,H,W,3]
__device__ float g_fuse[HW*Kdim];  // [H,W,K]
__device__ float g_u1  [HW*32];    // un1 output

// ---------------- colors [H,W,3K] -> [K,H,W,3] ------------------------------
__global__ void transpose_colors_kernel(const float* __restrict__ colors) {
    size_t i = (size_t)blockIdx.x * blockDim.x + threadIdx.x;
    if (i >= KHW * 3) return;
    int c   = (int)(i % 3);
    size_t r = i / 3;
    int k   = (int)(r >> 18);          // r / HW
    int pix = (int)(r & (HW - 1));     // r % HW
    g_ck[i] = colors[(size_t)pix * (3*Kdim) + k*3 + c];
}

// ---------------- fused MLP: 3 ->128 ->128 ->(+3)->128 ->32 -----------------
// 64 points per CTA, 128 threads. Hidden states ping-pong in dynamic smem.
__global__ void __launch_bounds__(128) mlp_kernel(
    const float* __restrict__ ray,  const float* __restrict__ zbufs,
    const float* __restrict__ W1,   const float* __restrict__ b1,
    const float* __restrict__ W2,   const float* __restrict__ b2,
    const float* __restrict__ W3,   const float* __restrict__ b3,
    const float* __restrict__ W4,   const float* __restrict__ b4)
{
    extern __shared__ float sh[];
    float* hA    = sh;              // 64*128
    float* hB    = sh + 8192;       // 64*128
    float* s_xyz = sh + 16384;      // 64*3
    float* s_dir = sh + 16576;      // 64*3
    float* s_msk = sh + 16768;      // 64
    const int tid = threadIdx.x;
    const size_t pt0 = (size_t)blockIdx.x * 64;

    if (tid < 64) {
        size_t pt = pt0 + tid;
        int k = (int)(pt >> 18);
        int r = (int)(pt & (HW - 1));
        const float* rp = ray + (size_t)r * 7;
        float z = zbufs[(size_t)r * Kdim + k];
        float t = z / rp[6];
        s_xyz[tid*3+0] = rp[0] + rp[3]*t;
        s_xyz[tid*3+1] = rp[1] + rp[4]*t;
        s_xyz[tid*3+2] = rp[2] + rp[5]*t;
        s_dir[tid*3+0] = rp[3];
        s_dir[tid*3+1] = rp[4];
        s_dir[tid*3+2] = rp[5];
        s_msk[tid] = (z > 0.0f) ? 1.0f : 0.0f;
    }
    __syncthreads();

    // ---- layer 1: 3 -> 128 (relu) : thread = output column
    {
        float w0 = W1[tid], w1 = W1[128+tid], w2 = W1[256+tid], b = b1[tid];
        for (int p = 0; p < 64; p++) {
            float v = b + s_xyz[p*3]*w0 + s_xyz[p*3+1]*w1 + s_xyz[p*3+2]*w2;
            hA[p*128 + tid] = fmaxf(v, 0.0f);
        }
    }
    __syncthreads();

    const int jb   = tid & 31;   // base output column
    const int pgrp = tid >> 5;   // 4 groups of 16 points

    // ---- layer 2: 128 -> 128 (relu), hA -> hB
    for (int pb = pgrp*16; pb < pgrp*16 + 16; pb += 8) {
        float acc[8][4];
        #pragma unroll
        for (int u = 0; u < 8; u++)
            #pragma unroll
            for (int q = 0; q < 4; q++) acc[u][q] = b2[jb + 32*q];
        for (int c = 0; c < 128; c += 4) {
            float wq[4][4];
            #pragma unroll
            for (int q = 0; q < 4; q++)
                #pragma unroll
                for (int ci = 0; ci < 4; ci++)
                    wq[q][ci] = W2[(c+ci)*128 + jb + 32*q];
            #pragma unroll
            for (int u = 0; u < 8; u++) {
                float4 v = *(const float4*)&hA[(pb+u)*128 + c];
                #pragma unroll
                for (int q = 0; q < 4; q++)
                    acc[u][q] += v.x*wq[q][0] + v.y*wq[q][1]
                               + v.z*wq[q][2] + v.w*wq[q][3];
            }
        }
        #pragma unroll
        for (int u = 0; u < 8; u++)
            #pragma unroll
            for (int q = 0; q < 4; q++)
                hB[(pb+u)*128 + jb + 32*q] = fmaxf(acc[u][q], 0.0f);
    }
    __syncthreads();

    // ---- layer 3: concat(h,dirs) 131 -> 128 (relu), hB -> hA
    for (int pb = pgrp*16; pb < pgrp*16 + 16; pb += 8) {
        float acc[8][4];
        #pragma unroll
        for (int u = 0; u < 8; u++)
            #pragma unroll
            for (int q = 0; q < 4; q++) acc[u][q] = b3[jb + 32*q];
        for (int c = 0; c < 128; c += 4) {
            float wq[4][4];
            #pragma unroll
            for (int q = 0; q < 4; q++)
                #pragma unroll
                for (int ci = 0; ci < 4; ci++)
                    wq[q][ci] = W3[(c+ci)*128 + jb + 32*q];
            #pragma unroll
            for (int u = 0; u < 8; u++) {
                float4 v = *(const float4*)&hB[(pb+u)*128 + c];
                #pragma unroll
                for (int q = 0; q < 4; q++)
                    acc[u][q] += v.x*wq[q][0] + v.y*wq[q][1]
                               + v.z*wq[q][2] + v.w*wq[q][3];
            }
        }
        // dirs rows 128..130
        float wd[3][4];
        #pragma unroll
        for (int q = 0; q < 4; q++) {
            wd[0][q] = W3[128*128 + jb + 32*q];
            wd[1][q] = W3[129*128 + jb + 32*q];
            wd[2][q] = W3[130*128 + jb + 32*q];
        }
        #pragma unroll
        for (int u = 0; u < 8; u++) {
            float d0 = s_dir[(pb+u)*3+0], d1 = s_dir[(pb+u)*3+1], d2 = s_dir[(pb+u)*3+2];
            #pragma unroll
            for (int q = 0; q < 4; q++)
                acc[u][q] += d0*wd[0][q] + d1*wd[1][q] + d2*wd[2][q];
        }
        #pragma unroll
        for (int u = 0; u < 8; u++)
            #pragma unroll
            for (int q = 0; q < 4; q++)
                hA[(pb+u)*128 + jb + 32*q] = fmaxf(acc[u][q], 0.0f);
    }
    __syncthreads();

    // ---- layer 4: 128 -> 32, mask, write fm channels 0..31
    {
        const int od = tid & 31;
        const int pg = tid >> 5;  // 16 points each
        float acc[16];
        #pragma unroll
        for (int u = 0; u < 16; u++) acc[u] = b4[od];
        for (int c = 0; c < 128; c += 4) {
            float w0 = W4[c*32+od], w1 = W4[(c+1)*32+od];
            float w2 = W4[(c+2)*32+od], w3 = W4[(c+3)*32+od];
            #pragma unroll
            for (int u = 0; u < 16; u++) {
                float4 v = *(const float4*)&hA[(pg*16+u)*128 + c];
                acc[u] += v.x*w0 + v.y*w1 + v.z*w2 + v.w*w3;
            }
        }
        #pragma unroll
        for (int u = 0; u < 16; u++) {
            int p = pg*16 + u;
            g_fm[(pt0 + p)*64 + od] = acc[u] * s_msk[p];
        }
    }
}

// ---------------- generic fused-tile 3x3 SAME conv --------------------------
// in: [N,H,W,CIN], wt: [3,3,CIN,COUT] (HWIO), out channel stride/offset params.
template<int CIN, int COUT, int CHK, int TH, int TW, int PPT, int CG, bool RELU>
__global__ void __launch_bounds__((TH*TW/PPT)*CG) conv3x3_kernel(
    const float* __restrict__ in, const float* __restrict__ wt,
    const float* __restrict__ bias, float* __restrict__ out,
    int ostride, int ooffs)
{
    constexpr int CPT = COUT / CG;
    constexpr int NT  = (TH*TW/PPT)*CG;
    __shared__ float s_in[TH+2][TW+2][CHK+1];
    __shared__ float s_wt[9][CHK][COUT];

    const int tid = threadIdx.x;
    const int n   = blockIdx.z;
    const int by  = blockIdx.y * TH;
    const int bx  = blockIdx.x * TW;
    const int cg  = tid % CG;
    const int pg  = tid / CG;
    const int p0  = pg * PPT;
    const int py  = p0 / TW;
    const int px0 = p0 % TW;

    float acc[PPT][CPT];
    #pragma unroll
    for (int u = 0; u < PPT; u++)
        #pragma unroll
        for (int u2 = 0; u2 < CPT; u2++) acc[u][u2] = bias[cg*CPT + u2];

    for (int c0 = 0; c0 < CIN; c0 += CHK) {
        for (int i = tid; i < (TH+2)*(TW+2)*CHK; i += NT) {
            int ci = i % CHK;
            int xy = i / CHK;
            int xx = xy % (TW+2);
            int yy = xy / (TW+2);
            int gy = by + yy - 1, gx = bx + xx - 1;
            float v = 0.0f;
            if (gy >= 0 && gy < Hdim && gx >= 0 && gx < Wdim)
                v = in[(((size_t)n*Hdim + gy)*Wdim + gx)*CIN + c0 + ci];
            s_in[yy][xx][ci] = v;
        }
        for (int i = tid; i < 9*CHK*COUT; i += NT) {
            int co = i % COUT;
            int rc = i / COUT;
            int ci = rc % CHK;
            int tap = rc / CHK;
            s_wt[tap][ci][co] = wt[((size_t)tap*CIN + c0 + ci)*COUT + co];
        }
        __syncthreads();

        for (int tap = 0; tap < 9; tap++) {
            int ky = tap / 3, kx = tap % 3;
            #pragma unroll
            for (int ci = 0; ci < CHK; ci++) {
                float wv[CPT];
                #pragma unroll
                for (int u2 = 0; u2 < CPT; u2++) wv[u2] = s_wt[tap][ci][cg*CPT + u2];
                #pragma unroll
                for (int u = 0; u < PPT; u++) {
                    float v = s_in[py+ky][px0+u+kx][ci];
                    #pragma unroll
                    for (int u2 = 0; u2 < CPT; u2++) acc[u][u2] += v * wv[u2];
                }
            }
        }
        __syncthreads();
    }

    #pragma unroll
    for (int u = 0; u < PPT; u++) {
        int gy = by + py, gx = bx + px0 + u;
        size_t ob = (((size_t)n*Hdim + gy)*Wdim + gx)*(size_t)ostride + ooffs + cg*CPT;
        #pragma unroll
        for (int u2 = 0; u2 < CPT; u2++)
            out[ob + u2] = RELU ? fmaxf(acc[u][u2], 0.0f) : acc[u][u2];
    }
}

// ---------------- sigmoid + cumprod alpha compositing ------------------------
__global__ void composite_kernel() {
    size_t pt = (size_t)blockIdx.x * blockDim.x + threadIdx.x;
    if (pt >= KHW) return;
    const float4* f4 = (const float4*)(g_fm + pt*64);
    const float4* m4 = (const float4*)(g_m  + pt*64);
    float alpha = 1.0f, acc = 0.0f;
    #pragma unroll 4
    for (int i = 0; i < 16; i++) {
        float4 f = f4[i], mr = m4[i];
        float m;
        m = 1.0f/(1.0f+expf(-mr.x)); acc += f.x*m*alpha; alpha *= (1.0f-m);
        m = 1.0f/(1.0f+expf(-mr.y)); acc += f.y*m*alpha; alpha *= (1.0f-m);
        m = 1.0f/(1.0f+expf(-mr.z)); acc += f.z*m*alpha; alpha *= (1.0f-m);
        m = 1.0f/(1.0f+expf(-mr.w)); acc += f.w*m*alpha; alpha *= (1.0f-m);
    }
    int k = (int)(pt >> 18);
    int r = (int)(pt & (HW - 1));
    g_fuse[(size_t)r*Kdim + k] = acc;   // [H,W,K]
}

// ---------------- launch orchestration ---------------------------------------
extern "C" void kernel_launch(void* const* d_in, const int* in_sizes, int n_in,
                              void* d_out, int out_size)
{
    const float* colors = (const float*)d_in[0];
    const float* ray    = (const float*)d_in[1];
    const float* zbufs  = (const float*)d_in[2];
    const float* W1 = (const float*)d_in[3];   const float* b1 = (const float*)d_in[4];
    const float* W2 = (const float*)d_in[5];   const float* b2 = (const float*)d_in[6];
    const float* W3 = (const float*)d_in[7];   const float* b3 = (const float*)d_in[8];
    const float* W4 = (const float*)d_in[9];   const float* b4 = (const float*)d_in[10];
    const float* ks1 = (const float*)d_in[11]; const float* bs1 = (const float*)d_in[12];
    const float* ks2 = (const float*)d_in[13]; const float* bs2 = (const float*)d_in[14];
    const float* km1 = (const float*)d_in[15]; const float* bm1 = (const float*)d_in[16];
    const float* km2 = (const float*)d_in[17]; const float* bm2 = (const float*)d_in[18];
    const float* ku1 = (const float*)d_in[19]; const float* bu1 = (const float*)d_in[20];
    const float* ku2 = (const float*)d_in[21]; const float* bu2 = (const float*)d_in[22];
    float* out = (float*)d_out;

    float *fm, *tmp, *mbuf, *ck, *fuse, *u1;
    cudaGetSymbolAddress((void**)&fm,   g_fm);
    cudaGetSymbolAddress((void**)&tmp,  g_tmp);
    cudaGetSymbolAddress((void**)&mbuf, g_m);
    cudaGetSymbolAddress((void**)&ck,   g_ck);
    cudaGetSymbolAddress((void**)&fuse, g_fuse);
    cudaGetSymbolAddress((void**)&u1,   g_u1);

    const int mlp_smem = (2*64*128 + 64*3*2 + 64) * (int)sizeof(float);  // 67328
    cudaFuncSetAttribute(mlp_kernel, cudaFuncAttributeMaxDynamicSharedMemorySize, mlp_smem);

    // 1. colors -> [K,H,W,3]
    transpose_colors_kernel<<<(unsigned)((KHW*3 + 255)/256), 256>>>(colors);

    // 2. radiance-mapping MLP -> fm ch 0..31 (masked)
    mlp_kernel<<<(unsigned)(KHW/64), 128, mlp_smem>>>(ray, zbufs, W1,b1, W2,b2, W3,b3, W4,b4);

    // 3. sup conv1: 3->32, relu -> tmp (stride 32)
    conv3x3_kernel<3,32,3,16,16,4,2,true><<<dim3(32,32,8), 128>>>(ck, ks1, bs1, tmp, 32, 0);
    // 4. sup conv2: 32->32 -> fm ch 32..63
    conv3x3_kernel<32,32,16,16,16,4,2,false><<<dim3(32,32,8), 128>>>(tmp, ks2, bs2, fm, 64, 32);

    // 5. mpn conv1: 64->64, relu -> tmp (stride 64)
    conv3x3_kernel<64,64,8,8,16,4,4,true><<<dim3(32,64,8), 128>>>(fm, km1, bm1, tmp, 64, 0);
    // 6. mpn conv2: 64->64 -> mbuf (raw logits)
    conv3x3_kernel<64,64,8,8,16,4,4,false><<<dim3(32,64,8), 128>>>(tmp, km2, bm2, mbuf, 64, 0);

    // 7. sigmoid + cumprod compositing -> fuse [H,W,K]
    composite_kernel<<<(unsigned)((KHW + 255)/256), 256>>>();

    // 8. un conv1: 8->32, relu
    conv3x3_kernel<8,32,8,16,16,4,2,true><<<dim3(32,32,1), 128>>>(fuse, ku1, bu1, u1, 32, 0);
    // 9. un conv2: 32->3 -> output
    conv3x3_kernel<32,3,16,16,16,4,1,false><<<dim3(32,32,1), 64>>>(u1, ku2, bu2, out, 3, 0);

    (void)in_sizes; (void)n_in; (void)out_size;
}

// round 2
// speedup vs baseline: 1.0028x; 1.0028x over previous
#include <cuda_runtime.h>
#include <math.h>

#define Hdim 512
#define Wdim 512
#define Kdim 8
#define HW   (Hdim*Wdim)          // 262144
#define KHW  ((size_t)Kdim*HW)    // 2097152

// ---------------- scratch (device globals; no runtime allocation) ----------
__device__ float g_fm  [KHW*64];   // [K,H,W,64] : ch 0..31 = MLP feat, 32..63 = color feat
__device__ float g_tmp [KHW*64];   // generic intermediate
__device__ float g_m   [KHW*64];   // mpn2 raw logits
__device__ float g_ck  [KHW*3];    // colors transposed to [K,H,W,3]
__device__ float g_fuse[HW*Kdim];  // [H,W,K]
__device__ float g_u1  [HW*32];    // un1 output

// ---------------- colors [H,W,3K] -> [K,H,W,3] ------------------------------
__global__ void transpose_colors_kernel(const float* __restrict__ colors) {
    size_t i = (size_t)blockIdx.x * blockDim.x + threadIdx.x;
    if (i >= KHW * 3) return;
    int c   = (int)(i % 3);
    size_t r = i / 3;
    int k   = (int)(r >> 18);          // r / HW
    int pix = (int)(r & (HW - 1));     // r % HW
    g_ck[i] = colors[(size_t)pix * (3*Kdim) + k*3 + c];
}

// ---------------- fused MLP: 3 ->128 ->128 ->(+3)->128 ->32 -----------------
// 64 points per CTA, 128 threads. Hidden states ping-pong in dynamic smem.
__global__ void __launch_bounds__(128) mlp_kernel(
    const float* __restrict__ ray,  const float* __restrict__ zbufs,
    const float* __restrict__ W1,   const float* __restrict__ b1,
    const float* __restrict__ W2,   const float* __restrict__ b2,
    const float* __restrict__ W3,   const float* __restrict__ b3,
    const float* __restrict__ W4,   const float* __restrict__ b4)
{
    extern __shared__ float sh[];
    float* hA    = sh;              // 64*128
    float* hB    = sh + 8192;       // 64*128
    float* s_xyz = sh + 16384;      // 64*3
    float* s_dir = sh + 16576;      // 64*3
    float* s_msk = sh + 16768;      // 64
    const int tid = threadIdx.x;
    const size_t pt0 = (size_t)blockIdx.x * 64;

    if (tid < 64) {
        size_t pt = pt0 + tid;
        int k = (int)(pt >> 18);
        int r = (int)(pt & (HW - 1));
        const float* rp = ray + (size_t)r * 7;
        float z = zbufs[(size_t)r * Kdim + k];
        float t = z / rp[6];
        s_xyz[tid*3+0] = rp[0] + rp[3]*t;
        s_xyz[tid*3+1] = rp[1] + rp[4]*t;
        s_xyz[tid*3+2] = rp[2] + rp[5]*t;
        s_dir[tid*3+0] = rp[3];
        s_dir[tid*3+1] = rp[4];
        s_dir[tid*3+2] = rp[5];
        s_msk[tid] = (z > 0.0f) ? 1.0f : 0.0f;
    }
    __syncthreads();

    // ---- layer 1: 3 -> 128 (relu) : thread = output column
    {
        float w0 = W1[tid], w1 = W1[128+tid], w2 = W1[256+tid], b = b1[tid];
        for (int p = 0; p < 64; p++) {
            float v = b + s_xyz[p*3]*w0 + s_xyz[p*3+1]*w1 + s_xyz[p*3+2]*w2;
            hA[p*128 + tid] = fmaxf(v, 0.0f);
        }
    }
    __syncthreads();

    const int jb   = tid & 31;   // base output column
    const int pgrp = tid >> 5;   // 4 groups of 16 points

    // ---- layer 2: 128 -> 128 (relu), hA -> hB
    for (int pb = pgrp*16; pb < pgrp*16 + 16; pb += 8) {
        float acc[8][4];
        #pragma unroll
        for (int u = 0; u < 8; u++)
            #pragma unroll
            for (int q = 0; q < 4; q++) acc[u][q] = b2[jb + 32*q];
        for (int c = 0; c < 128; c += 4) {
            float wq[4][4];
            #pragma unroll
            for (int q = 0; q < 4; q++)
                #pragma unroll
                for (int ci = 0; ci < 4; ci++)
                    wq[q][ci] = W2[(c+ci)*128 + jb + 32*q];
            #pragma unroll
            for (int u = 0; u < 8; u++) {
                float4 v = *(const float4*)&hA[(pb+u)*128 + c];
                #pragma unroll
                for (int q = 0; q < 4; q++)
                    acc[u][q] += v.x*wq[q][0] + v.y*wq[q][1]
                               + v.z*wq[q][2] + v.w*wq[q][3];
            }
        }
        #pragma unroll
        for (int u = 0; u < 8; u++)
            #pragma unroll
            for (int q = 0; q < 4; q++)
                hB[(pb+u)*128 + jb + 32*q] = fmaxf(acc[u][q], 0.0f);
    }
    __syncthreads();

    // ---- layer 3: concat(h,dirs) 131 -> 128 (relu), hB -> hA
    for (int pb = pgrp*16; pb < pgrp*16 + 16; pb += 8) {
        float acc[8][4];
        #pragma unroll
        for (int u = 0; u < 8; u++)
            #pragma unroll
            for (int q = 0; q < 4; q++) acc[u][q] = b3[jb + 32*q];
        for (int c = 0; c < 128; c += 4) {
            float wq[4][4];
            #pragma unroll
            for (int q = 0; q < 4; q++)
                #pragma unroll
                for (int ci = 0; ci < 4; ci++)
                    wq[q][ci] = W3[(c+ci)*128 + jb + 32*q];
            #pragma unroll
            for (int u = 0; u < 8; u++) {
                float4 v = *(const float4*)&hB[(pb+u)*128 + c];
                #pragma unroll
                for (int q = 0; q < 4; q++)
                    acc[u][q] += v.x*wq[q][0] + v.y*wq[q][1]
                               + v.z*wq[q][2] + v.w*wq[q][3];
            }
        }
        // dirs rows 128..130
        float wd[3][4];
        #pragma unroll
        for (int q = 0; q < 4; q++) {
            wd[0][q] = W3[128*128 + jb + 32*q];
            wd[1][q] = W3[129*128 + jb + 32*q];
            wd[2][q] = W3[130*128 + jb + 32*q];
        }
        #pragma unroll
        for (int u = 0; u < 8; u++) {
            float d0 = s_dir[(pb+u)*3+0], d1 = s_dir[(pb+u)*3+1], d2 = s_dir[(pb+u)*3+2];
            #pragma unroll
            for (int q = 0; q < 4; q++)
                acc[u][q] += d0*wd[0][q] + d1*wd[1][q] + d2*wd[2][q];
        }
        #pragma unroll
        for (int u = 0; u < 8; u++)
            #pragma unroll
            for (int q = 0; q < 4; q++)
                hA[(pb+u)*128 + jb + 32*q] = fmaxf(acc[u][q], 0.0f);
    }
    __syncthreads();

    // ---- layer 4: 128 -> 32, mask, write fm channels 0..31
    {
        const int od = tid & 31;
        const int pg = tid >> 5;  // 16 points each
        float acc[16];
        #pragma unroll
        for (int u = 0; u < 16; u++) acc[u] = b4[od];
        for (int c = 0; c < 128; c += 4) {
            float w0 = W4[c*32+od], w1 = W4[(c+1)*32+od];
            float w2 = W4[(c+2)*32+od], w3 = W4[(c+3)*32+od];
            #pragma unroll
            for (int u = 0; u < 16; u++) {
                float4 v = *(const float4*)&hA[(pg*16+u)*128 + c];
                acc[u] += v.x*w0 + v.y*w1 + v.z*w2 + v.w*w3;
            }
        }
        #pragma unroll
        for (int u = 0; u < 16; u++) {
            int p = pg*16 + u;
            g_fm[(pt0 + p)*64 + od] = acc[u] * s_msk[p];
        }
    }
}

// ---------------- generic fused-tile 3x3 SAME conv --------------------------
// in: [N,H,W,CIN], wt: [3,3,CIN,COUT] (HWIO), out channel stride/offset params.
template<int CIN, int COUT, int CHK, int TH, int TW, int PPT, int CG, bool RELU>
__global__ void __launch_bounds__((TH*TW/PPT)*CG) conv3x3_kernel(
    const float* __restrict__ in, const float* __restrict__ wt,
    const float* __restrict__ bias, float* __restrict__ out,
    int ostride, int ooffs)
{
    constexpr int CPT = COUT / CG;
    constexpr int NT  = (TH*TW/PPT)*CG;
    __shared__ float s_in[TH+2][TW+2][CHK+1];
    __shared__ float s_wt[9][CHK][COUT];

    const int tid = threadIdx.x;
    const int n   = blockIdx.z;
    const int by  = blockIdx.y * TH;
    const int bx  = blockIdx.x * TW;
    const int cg  = tid % CG;
    const int pg  = tid / CG;
    const int p0  = pg * PPT;
    const int py  = p0 / TW;
    const int px0 = p0 % TW;

    float acc[PPT][CPT];
    #pragma unroll
    for (int u = 0; u < PPT; u++)
        #pragma unroll
        for (int u2 = 0; u2 < CPT; u2++) acc[u][u2] = bias[cg*CPT + u2];

    for (int c0 = 0; c0 < CIN; c0 += CHK) {
        for (int i = tid; i < (TH+2)*(TW+2)*CHK; i += NT) {
            int ci = i % CHK;
            int xy = i / CHK;
            int xx = xy % (TW+2);
            int yy = xy / (TW+2);
            int gy = by + yy - 1, gx = bx + xx - 1;
            float v = 0.0f;
            if (gy >= 0 && gy < Hdim && gx >= 0 && gx < Wdim)
                v = in[(((size_t)n*Hdim + gy)*Wdim + gx)*CIN + c0 + ci];
            s_in[yy][xx][ci] = v;
        }
        for (int i = tid; i < 9*CHK*COUT; i += NT) {
            int co = i % COUT;
            int rc = i / COUT;
            int ci = rc % CHK;
            int tap = rc / CHK;
            s_wt[tap][ci][co] = wt[((size_t)tap*CIN + c0 + ci)*COUT + co];
        }
        __syncthreads();

        for (int tap = 0; tap < 9; tap++) {
            int ky = tap / 3, kx = tap % 3;
            #pragma unroll
            for (int ci = 0; ci < CHK; ci++) {
                float wv[CPT];
                #pragma unroll
                for (int u2 = 0; u2 < CPT; u2++) wv[u2] = s_wt[tap][ci][cg*CPT + u2];
                #pragma unroll
                for (int u = 0; u < PPT; u++) {
                    float v = s_in[py+ky][px0+u+kx][ci];
                    #pragma unroll
                    for (int u2 = 0; u2 < CPT; u2++) acc[u][u2] += v * wv[u2];
                }
            }
        }
        __syncthreads();
    }

    #pragma unroll
    for (int u = 0; u < PPT; u++) {
        int gy = by + py, gx = bx + px0 + u;
        size_t ob = (((size_t)n*Hdim + gy)*Wdim + gx)*(size_t)ostride + ooffs + cg*CPT;
        #pragma unroll
        for (int u2 = 0; u2 < CPT; u2++)
            out[ob + u2] = RELU ? fmaxf(acc[u][u2], 0.0f) : acc[u][u2];
    }
}

// ---------------- sigmoid + cumprod alpha compositing ------------------------
__global__ void composite_kernel() {
    size_t pt = (size_t)blockIdx.x * blockDim.x + threadIdx.x;
    if (pt >= KHW) return;
    const float4* f4 = (const float4*)(g_fm + pt*64);
    const float4* m4 = (const float4*)(g_m  + pt*64);
    float alpha = 1.0f, acc = 0.0f;
    #pragma unroll 4
    for (int i = 0; i < 16; i++) {
        float4 f = f4[i], mr = m4[i];
        float m;
        m = 1.0f/(1.0f+expf(-mr.x)); acc += f.x*m*alpha; alpha *= (1.0f-m);
        m = 1.0f/(1.0f+expf(-mr.y)); acc += f.y*m*alpha; alpha *= (1.0f-m);
        m = 1.0f/(1.0f+expf(-mr.z)); acc += f.z*m*alpha; alpha *= (1.0f-m);
        m = 1.0f/(1.0f+expf(-mr.w)); acc += f.w*m*alpha; alpha *= (1.0f-m);
    }
    int k = (int)(pt >> 18);
    int r = (int)(pt & (HW - 1));
    g_fuse[(size_t)r*Kdim + k] = acc;   // [H,W,K]
}

// ---------------- launch orchestration ---------------------------------------
extern "C" void kernel_launch(void* const* d_in, const int* in_sizes, int n_in,
                              void* d_out, int out_size)
{
    const float* colors = (const float*)d_in[0];
    const float* ray    = (const float*)d_in[1];
    const float* zbufs  = (const float*)d_in[2];
    const float* W1 = (const float*)d_in[3];   const float* b1 = (const float*)d_in[4];
    const float* W2 = (const float*)d_in[5];   const float* b2 = (const float*)d_in[6];
    const float* W3 = (const float*)d_in[7];   const float* b3 = (const float*)d_in[8];
    const float* W4 = (const float*)d_in[9];   const float* b4 = (const float*)d_in[10];
    const float* ks1 = (const float*)d_in[11]; const float* bs1 = (const float*)d_in[12];
    const float* ks2 = (const float*)d_in[13]; const float* bs2 = (const float*)d_in[14];
    const float* km1 = (const float*)d_in[15]; const float* bm1 = (const float*)d_in[16];
    const float* km2 = (const float*)d_in[17]; const float* bm2 = (const float*)d_in[18];
    const float* ku1 = (const float*)d_in[19]; const float* bu1 = (const float*)d_in[20];
    const float* ku2 = (const float*)d_in[21]; const float* bu2 = (const float*)d_in[22];
    float* out = (float*)d_out;

    float *fm, *tmp, *mbuf, *ck, *fuse, *u1;
    cudaGetSymbolAddress((void**)&fm,   g_fm);
    cudaGetSymbolAddress((void**)&tmp,  g_tmp);
    cudaGetSymbolAddress((void**)&mbuf, g_m);
    cudaGetSymbolAddress((void**)&ck,   g_ck);
    cudaGetSymbolAddress((void**)&fuse, g_fuse);
    cudaGetSymbolAddress((void**)&u1,   g_u1);

    const int mlp_smem = (2*64*128 + 64*3*2 + 64) * (int)sizeof(float);  // 67328
    cudaFuncSetAttribute(mlp_kernel, cudaFuncAttributeMaxDynamicSharedMemorySize, mlp_smem);

    // 1. colors -> [K,H,W,3]
    transpose_colors_kernel<<<(unsigned)((KHW*3 + 255)/256), 256>>>(colors);

    // 2. radiance-mapping MLP -> fm ch 0..31 (masked)
    mlp_kernel<<<(unsigned)(KHW/64), 128, mlp_smem>>>(ray, zbufs, W1,b1, W2,b2, W3,b3, W4,b4);

    // 3. sup conv1: 3->32, relu -> tmp (stride 32)
    conv3x3_kernel<3,32,3,16,16,4,2,true><<<dim3(32,32,8), 128>>>(ck, ks1, bs1, tmp, 32, 0);
    // 4. sup conv2: 32->32 -> fm ch 32..63
    conv3x3_kernel<32,32,16,16,16,4,2,false><<<dim3(32,32,8), 128>>>(tmp, ks2, bs2, fm, 64, 32);

    // 5. mpn conv1: 64->64, relu -> tmp (stride 64)
    conv3x3_kernel<64,64,8,8,16,4,4,true><<<dim3(32,64,8), 128>>>(fm, km1, bm1, tmp, 64, 0);
    // 6. mpn conv2: 64->64 -> mbuf (raw logits)
    conv3x3_kernel<64,64,8,8,16,4,4,false><<<dim3(32,64,8), 128>>>(tmp, km2, bm2, mbuf, 64, 0);

    // 7. sigmoid + cumprod compositing -> fuse [H,W,K]
    composite_kernel<<<(unsigned)((KHW + 255)/256), 256>>>();

    // 8. un conv1: 8->32, relu
    conv3x3_kernel<8,32,8,16,16,4,2,true><<<dim3(32,32,1), 128>>>(fuse, ku1, bu1, u1, 32, 0);
    // 9. un conv2: 32->3 -> output
    conv3x3_kernel<32,3,16,16,16,4,1,false><<<dim3(32,32,1), 64>>>(u1, ku2, bu2, out, 3, 0);

    (void)in_sizes; (void)n_in; (void)out_size;
}

// round 12
// speedup vs baseline: 1.3665x; 1.3627x over previous
#include <cuda_runtime.h>
#include <math.h>
#include <stdint.h>
#include <mma.h>

using namespace nvcuda;

#define Hdim 512
#define Wdim 512
#define Kdim 8
#define HW   (Hdim*Wdim)          // 262144
#define KHW  ((size_t)Kdim*HW)    // 2097152

// ---------------- scratch (device globals; no runtime allocation) ----------
__device__ float g_fm  [KHW*64];   // [K,H,W,64] : ch 0..31 = MLP feat, 32..63 = color feat
__device__ float g_t1  [KHW*64];   // mpn1 output
__device__ float g_m   [KHW*64];   // mpn2 raw logits
__device__ float g_ck  [KHW*3];    // colors transposed [K,H,W,3]
__device__ float g_tmp [KHW*32];   // sup1 output
__device__ float g_fuse[HW*Kdim];  // [H,W,K]
__device__ float g_u1  [HW*32];    // un1 output

// ======================= helpers ===========================================
__device__ __forceinline__ uint32_t cvt_tf32(float f){
    uint32_t u; asm("cvt.rna.tf32.f32 %0, %1;" : "=r"(u) : "f"(f)); return u;
}
__device__ __forceinline__ float tf32r(float f){ return __uint_as_float(cvt_tf32(f)); }

// ---------------- colors [H,W,3K] -> [K,H,W,3] ------------------------------
__global__ void transpose_colors_kernel(const float* __restrict__ colors) {
    size_t i = (size_t)blockIdx.x * blockDim.x + threadIdx.x;
    if (i >= KHW * 3) return;
    int c   = (int)(i % 3);
    size_t r = i / 3;
    int k   = (int)(r >> 18);
    int pix = (int)(r & (HW - 1));
    g_ck[i] = colors[(size_t)pix * (3*Kdim) + k*3 + c];
}

// ---------------- fused MLP: 3 ->128 ->128 ->(+3)->128 ->32 -----------------
__global__ void __launch_bounds__(128) mlp_kernel(
    const float* __restrict__ ray,  const float* __restrict__ zbufs,
    const float* __restrict__ W1,   const float* __restrict__ b1,
    const float* __restrict__ W2,   const float* __restrict__ b2,
    const float* __restrict__ W3,   const float* __restrict__ b3,
    const float* __restrict__ W4,   const float* __restrict__ b4)
{
    extern __shared__ float sh[];
    float* hA    = sh;
    float* hB    = sh + 8192;
    float* s_xyz = sh + 16384;
    float* s_dir = sh + 16576;
    float* s_msk = sh + 16768;
    const int tid = threadIdx.x;
    const size_t pt0 = (size_t)blockIdx.x * 64;

    if (tid < 64) {
        size_t pt = pt0 + tid;
        int k = (int)(pt >> 18);
        int r = (int)(pt & (HW - 1));
        const float* rp = ray + (size_t)r * 7;
        float z = zbufs[(size_t)r * Kdim + k];
        float t = z / rp[6];
        s_xyz[tid*3+0] = rp[0] + rp[3]*t;
        s_xyz[tid*3+1] = rp[1] + rp[4]*t;
        s_xyz[tid*3+2] = rp[2] + rp[5]*t;
        s_dir[tid*3+0] = rp[3];
        s_dir[tid*3+1] = rp[4];
        s_dir[tid*3+2] = rp[5];
        s_msk[tid] = (z > 0.0f) ? 1.0f : 0.0f;
    }
    __syncthreads();

    {
        float w0 = W1[tid], w1 = W1[128+tid], w2 = W1[256+tid], b = b1[tid];
        for (int p = 0; p < 64; p++) {
            float v = b + s_xyz[p*3]*w0 + s_xyz[p*3+1]*w1 + s_xyz[p*3+2]*w2;
            hA[p*128 + tid] = fmaxf(v, 0.0f);
        }
    }
    __syncthreads();

    const int jb   = tid & 31;
    const int pgrp = tid >> 5;

    for (int pb = pgrp*16; pb < pgrp*16 + 16; pb += 8) {
        float acc[8][4];
        #pragma unroll
        for (int u = 0; u < 8; u++)
            #pragma unroll
            for (int q = 0; q < 4; q++) acc[u][q] = b2[jb + 32*q];
        for (int c = 0; c < 128; c += 4) {
            float wq[4][4];
            #pragma unroll
            for (int q = 0; q < 4; q++)
                #pragma unroll
                for (int ci = 0; ci < 4; ci++)
                    wq[q][ci] = W2[(c+ci)*128 + jb + 32*q];
            #pragma unroll
            for (int u = 0; u < 8; u++) {
                float4 v = *(const float4*)&hA[(pb+u)*128 + c];
                #pragma unroll
                for (int q = 0; q < 4; q++)
                    acc[u][q] += v.x*wq[q][0] + v.y*wq[q][1]
                               + v.z*wq[q][2] + v.w*wq[q][3];
            }
        }
        #pragma unroll
        for (int u = 0; u < 8; u++)
            #pragma unroll
            for (int q = 0; q < 4; q++)
                hB[(pb+u)*128 + jb + 32*q] = fmaxf(acc[u][q], 0.0f);
    }
    __syncthreads();

    for (int pb = pgrp*16; pb < pgrp*16 + 16; pb += 8) {
        float acc[8][4];
        #pragma unroll
        for (int u = 0; u < 8; u++)
            #pragma unroll
            for (int q = 0; q < 4; q++) acc[u][q] = b3[jb + 32*q];
        for (int c = 0; c < 128; c += 4) {
            float wq[4][4];
            #pragma unroll
            for (int q = 0; q < 4; q++)
                #pragma unroll
                for (int ci = 0; ci < 4; ci++)
                    wq[q][ci] = W3[(c+ci)*128 + jb + 32*q];
            #pragma unroll
            for (int u = 0; u < 8; u++) {
                float4 v = *(const float4*)&hB[(pb+u)*128 + c];
                #pragma unroll
                for (int q = 0; q < 4; q++)
                    acc[u][q] += v.x*wq[q][0] + v.y*wq[q][1]
                               + v.z*wq[q][2] + v.w*wq[q][3];
            }
        }
        float wd[3][4];
        #pragma unroll
        for (int q = 0; q < 4; q++) {
            wd[0][q] = W3[128*128 + jb + 32*q];
            wd[1][q] = W3[129*128 + jb + 32*q];
            wd[2][q] = W3[130*128 + jb + 32*q];
        }
        #pragma unroll
        for (int u = 0; u < 8; u++) {
            float d0 = s_dir[(pb+u)*3+0], d1 = s_dir[(pb+u)*3+1], d2 = s_dir[(pb+u)*3+2];
            #pragma unroll
            for (int q = 0; q < 4; q++)
                acc[u][q] += d0*wd[0][q] + d1*wd[1][q] + d2*wd[2][q];
        }
        #pragma unroll
        for (int u = 0; u < 8; u++)
            #pragma unroll
            for (int q = 0; q < 4; q++)
                hA[(pb+u)*128 + jb + 32*q] = fmaxf(acc[u][q], 0.0f);
    }
    __syncthreads();

    {
        const int od = tid & 31;
        const int pg = tid >> 5;
        float acc[16];
        #pragma unroll
        for (int u = 0; u < 16; u++) acc[u] = b4[od];
        for (int c = 0; c < 128; c += 4) {
            float w0 = W4[c*32+od], w1 = W4[(c+1)*32+od];
            float w2 = W4[(c+2)*32+od], w3 = W4[(c+3)*32+od];
            #pragma unroll
            for (int u = 0; u < 16; u++) {
                float4 v = *(const float4*)&hA[(pg*16+u)*128 + c];
                acc[u] += v.x*w0 + v.y*w1 + v.z*w2 + v.w*w3;
            }
        }
        #pragma unroll
        for (int u = 0; u < 16; u++) {
            int p = pg*16 + u;
            g_fm[(pt0 + p)*64 + od] = acc[u] * s_msk[p];
        }
    }
}

// ---------------- generic fused-tile 3x3 SAME conv (SIMT) -------------------
// NOTE: epilogue restored to R1 form: "+ ooffs + cg*CPT" (the R4-R10 regression)
template<int CIN, int COUT, int CHK, int TH, int TW, int PPT, int CG, bool RELU>
__global__ void __launch_bounds__((TH*TW/PPT)*CG) conv3x3_kernel(
    const float* __restrict__ in, const float* __restrict__ wt,
    const float* __restrict__ bias, float* __restrict__ out,
    int ostride, int ooffs)
{
    constexpr int CPT = COUT / CG;
    constexpr int NT  = (TH*TW/PPT)*CG;
    __shared__ float s_in[TH+2][TW+2][CHK+1];
    __shared__ float s_wt[9][CHK][COUT];

    const int tid = threadIdx.x;
    const int n   = blockIdx.z;
    const int by  = blockIdx.y * TH;
    const int bx  = blockIdx.x * TW;
    const int cg  = tid % CG;
    const int pg  = tid / CG;
    const int p0  = pg * PPT;
    const int py  = p0 / TW;
    const int px0 = p0 % TW;

    float acc[PPT][CPT];
    #pragma unroll
    for (int u = 0; u < PPT; u++)
        #pragma unroll
        for (int u2 = 0; u2 < CPT; u2++) acc[u][u2] = bias[cg*CPT + u2];

    for (int c0 = 0; c0 < CIN; c0 += CHK) {
        for (int i = tid; i < (TH+2)*(TW+2)*CHK; i += NT) {
            int ci = i % CHK;
            int xy = i / CHK;
            int xx = xy % (TW+2);
            int yy = xy / (TW+2);
            int gy = by + yy - 1, gx = bx + xx - 1;
            float v = 0.0f;
            if (gy >= 0 && gy < Hdim && gx >= 0 && gx < Wdim)
                v = in[(((size_t)n*Hdim + gy)*Wdim + gx)*CIN + c0 + ci];
            s_in[yy][xx][ci] = v;
        }
        for (int i = tid; i < 9*CHK*COUT; i += NT) {
            int co = i % COUT;
            int rc = i / COUT;
            int ci = rc % CHK;
            int tap = rc / CHK;
            s_wt[tap][ci][co] = wt[((size_t)tap*CIN + c0 + ci)*COUT + co];
        }
        __syncthreads();

        for (int tap = 0; tap < 9; tap++) {
            int ky = tap / 3, kx = tap % 3;
            #pragma unroll
            for (int ci = 0; ci < CHK; ci++) {
                float wv[CPT];
                #pragma unroll
                for (int u2 = 0; u2 < CPT; u2++) wv[u2] = s_wt[tap][ci][cg*CPT + u2];
                #pragma unroll
                for (int u = 0; u < PPT; u++) {
                    float v = s_in[py+ky][px0+u+kx][ci];
                    #pragma unroll
                    for (int u2 = 0; u2 < CPT; u2++) acc[u][u2] += v * wv[u2];
                }
            }
        }
        __syncthreads();
    }

    #pragma unroll
    for (int u = 0; u < PPT; u++) {
        int gy = by + py, gx = bx + px0 + u;
        size_t ob = (((size_t)n*Hdim + gy)*Wdim + gx)*(size_t)ostride + ooffs + cg*CPT;
        #pragma unroll
        for (int u2 = 0; u2 < CPT; u2++)
            out[ob + u2] = RELU ? fmaxf(acc[u][u2], 0.0f) : acc[u][u2];
    }
}

// ======================= wmma tf32 conv3x3 (64->64, inline weights) ==========
// CTA: 128-px W strip of one output row, all 64 couts. 8 warps: 4(m) x 2(n),
// each 2 m-frags x 2 n-frags. A staged per input row in smem (LDA=72 floats,
// 288B rows -> all fragment bases 32B aligned). B staged per-ky DIRECTLY from
// the original HWIO weight tensor (tf32-rounded) into smem layout
// [kl=kx*8+c8][co][kloc] (col-major k x n per kstep, ldb=8).
template<bool RELU>
__global__ void __launch_bounds__(256) conv_wmma64_kernel(
    const float* __restrict__ in,   // [K,H,W,64]
    const float* __restrict__ wt,   // [3,3,64,64] HWIO (fp32)
    const float* __restrict__ bias, // [64]
    float* __restrict__ out)
{
    constexpr int CIN = 64, COUT = 64, C8 = 8;
    constexpr int LDA = CIN + 8;                 // 72 floats = 288B rows
    constexpr int B_CHUNK = 3*C8*COUT*8;         // 12288 floats per ky
    extern __shared__ float smem[];
    float* sB = smem;                            // 12288 floats (also D staging)
    float* sA = smem + B_CHUNK;                  // 130*72 = 9360 floats

    const int tid = threadIdx.x, wid = tid >> 5;
    const int wm = wid & 3, wn = wid >> 2;
    const int kimg = blockIdx.z, y = blockIdx.y, x0 = blockIdx.x * 128;

    wmma::fragment<wmma::accumulator, 16, 16, 8, float> acc[2][2];
    #pragma unroll
    for (int mt = 0; mt < 2; mt++)
        #pragma unroll
        for (int nt = 0; nt < 2; nt++)
            wmma::fill_fragment(acc[mt][nt], 0.0f);

    for (int ky = 0; ky < 3; ky++) {
        __syncthreads();
        // stage A: input row y+ky-1, 130 px x 64 ch, tf32-rounded
        int gy = y + ky - 1;
        for (int i = tid; i < 130*16; i += 256) {
            int c4 = i & 15;
            int px = i >> 4;
            int gx = x0 + px - 1;
            float4 v = make_float4(0.f, 0.f, 0.f, 0.f);
            if (gy >= 0 && gy < Hdim && (unsigned)gx < (unsigned)Wdim)
                v = *(const float4*)(in + (((size_t)(kimg*Hdim + gy))*Wdim + gx)*CIN + c4*4);
            float4 r = make_float4(tf32r(v.x), tf32r(v.y), tf32r(v.z), tf32r(v.w));
            *(float4*)&sA[px*LDA + c4*4] = r;
        }
        // stage B for this ky: taps (ky,kx=0..2), straight from HWIO weights.
        for (int i = tid; i < B_CHUNK; i += 256) {
            int co   = i & 63;
            int r    = i >> 6;
            int kloc = r & 7;
            int kl   = r >> 3;        // 0..23 = kx*8 + c8
            int kx   = kl >> 3;
            int c8   = kl & 7;
            int ci   = c8*8 + kloc;
            float w = wt[((size_t)(ky*3 + kx)*CIN + ci)*COUT + co];
            sB[((kl*COUT) + co)*8 + kloc] = tf32r(w);
        }
        __syncthreads();

        for (int kx = 0; kx < 3; kx++) {
            #pragma unroll
            for (int c8 = 0; c8 < C8; c8++) {
                int kl = kx*C8 + c8;
                wmma::fragment<wmma::matrix_a, 16, 16, 8, wmma::precision::tf32, wmma::row_major> af[2];
                #pragma unroll
                for (int mt = 0; mt < 2; mt++)
                    wmma::load_matrix_sync(af[mt], &sA[(wm*32 + mt*16 + kx)*LDA + c8*8], LDA);
                #pragma unroll
                for (int nt = 0; nt < 2; nt++) {
                    wmma::fragment<wmma::matrix_b, 16, 16, 8, wmma::precision::tf32, wmma::col_major> bf;
                    wmma::load_matrix_sync(bf, &sB[(kl*COUT + wn*32 + nt*16)*8], 8);
                    #pragma unroll
                    for (int mt = 0; mt < 2; mt++)
                        wmma::mma_sync(acc[mt][nt], af[mt], bf, acc[mt][nt]);
                }
            }
        }
    }

    // epilogue: stage D in sB region, then bias(+relu) + coalesced write
    __syncthreads();
    #pragma unroll
    for (int mt = 0; mt < 2; mt++)
        #pragma unroll
        for (int nt = 0; nt < 2; nt++)
            wmma::store_matrix_sync(&sB[(wm*32 + mt*16)*COUT + wn*32 + nt*16],
                                    acc[mt][nt], COUT, wmma::mem_row_major);
    __syncthreads();

    for (int i = tid; i < 128*16; i += 256) {
        int c4 = i & 15;
        int px = i >> 4;
        float4 v = *(float4*)&sB[px*COUT + c4*4];
        v.x += bias[c4*4+0]; v.y += bias[c4*4+1];
        v.z += bias[c4*4+2]; v.w += bias[c4*4+3];
        if (RELU) {
            v.x = fmaxf(v.x, 0.f); v.y = fmaxf(v.y, 0.f);
            v.z = fmaxf(v.z, 0.f); v.w = fmaxf(v.w, 0.f);
        }
        *(float4*)(out + (((size_t)(kimg*Hdim + y))*Wdim + (x0 + px))*64 + c4*4) = v;
    }
}

// ---------------- sigmoid + cumprod alpha compositing ------------------------
__global__ void composite_kernel() {
    size_t pt = (size_t)blockIdx.x * blockDim.x + threadIdx.x;
    if (pt >= KHW) return;
    const float4* f4 = (const float4*)(g_fm + pt*64);
    const float4* m4 = (const float4*)(g_m  + pt*64);
    float alpha = 1.0f, acc = 0.0f;
    #pragma unroll 4
    for (int i = 0; i < 16; i++) {
        float4 f = f4[i], mr = m4[i];
        float m;
        m = 1.0f/(1.0f+expf(-mr.x)); acc += f.x*m*alpha; alpha *= (1.0f-m);
        m = 1.0f/(1.0f+expf(-mr.y)); acc += f.y*m*alpha; alpha *= (1.0f-m);
        m = 1.0f/(1.0f+expf(-mr.z)); acc += f.z*m*alpha; alpha *= (1.0f-m);
        m = 1.0f/(1.0f+expf(-mr.w)); acc += f.w*m*alpha; alpha *= (1.0f-m);
    }
    int k = (int)(pt >> 18);
    int pix = (int)(pt & (HW - 1));
    g_fuse[(size_t)pix*Kdim + k] = acc;   // [H,W,K]
}

// ---------------- launch orchestration ---------------------------------------
extern "C" void kernel_launch(void* const* d_in, const int* in_sizes, int n_in,
                              void* d_out, int out_size)
{
    const float* colors = (const float*)d_in[0];
    const float* ray    = (const float*)d_in[1];
    const float* zbufs  = (const float*)d_in[2];
    const float* W1 = (const float*)d_in[3];   const float* b1 = (const float*)d_in[4];
    const float* W2 = (const float*)d_in[5];   const float* b2 = (const float*)d_in[6];
    const float* W3 = (const float*)d_in[7];   const float* b3 = (const float*)d_in[8];
    const float* W4 = (const float*)d_in[9];   const float* b4 = (const float*)d_in[10];
    const float* ks1 = (const float*)d_in[11]; const float* bs1 = (const float*)d_in[12];
    const float* ks2 = (const float*)d_in[13]; const float* bs2 = (const float*)d_in[14];
    const float* km1 = (const float*)d_in[15]; const float* bm1 = (const float*)d_in[16];
    const float* km2 = (const float*)d_in[17]; const float* bm2 = (const float*)d_in[18];
    const float* ku1 = (const float*)d_in[19]; const float* bu1 = (const float*)d_in[20];
    const float* ku2 = (const float*)d_in[21]; const float* bu2 = (const float*)d_in[22];
    float* out = (float*)d_out;

    float *fm, *t1, *mbuf, *ck, *fuse, *u1, *tmp;
    cudaGetSymbolAddress((void**)&fm,   g_fm);
    cudaGetSymbolAddress((void**)&t1,   g_t1);
    cudaGetSymbolAddress((void**)&mbuf, g_m);
    cudaGetSymbolAddress((void**)&ck,   g_ck);
    cudaGetSymbolAddress((void**)&fuse, g_fuse);
    cudaGetSymbolAddress((void**)&u1,   g_u1);
    cudaGetSymbolAddress((void**)&tmp,  g_tmp);

    const int mlp_smem = (2*64*128 + 64*3*2 + 64) * (int)sizeof(float);
    cudaFuncSetAttribute(mlp_kernel, cudaFuncAttributeMaxDynamicSharedMemorySize, mlp_smem);

    // wmma smem: B chunk 12288 + A 9360 floats = 21648 floats = 86592 B
    const int wsmem = (3*8*64*8 + 130*72) * (int)sizeof(float);
    cudaFuncSetAttribute(conv_wmma64_kernel<true>,
                         cudaFuncAttributeMaxDynamicSharedMemorySize, wsmem);
    cudaFuncSetAttribute(conv_wmma64_kernel<false>,
                         cudaFuncAttributeMaxDynamicSharedMemorySize, wsmem);

    // 1. colors -> [K,H,W,3]
    transpose_colors_kernel<<<(unsigned)((KHW*3 + 255)/256), 256>>>(colors);

    // 2. radiance-mapping MLP -> fm ch 0..31 (masked)
    mlp_kernel<<<(unsigned)(KHW/64), 128, mlp_smem>>>(ray, zbufs, W1,b1, W2,b2, W3,b3, W4,b4);

    // 3. sup conv1: 3->32, relu -> tmp (SIMT, R1 config)
    conv3x3_kernel<3,32,3,16,16,4,2,true><<<dim3(32,32,8), 128>>>(ck, ks1, bs1, tmp, 32, 0);
    // 4. sup conv2: 32->32 -> fm ch 32..63 (SIMT, R1 config)
    conv3x3_kernel<32,32,16,16,16,4,2,false><<<dim3(32,32,8), 128>>>(tmp, ks2, bs2, fm, 64, 32);

    // 5. mpn conv1 (wmma tf32, inline weights): 64->64, relu -> t1
    conv_wmma64_kernel<true><<<dim3(4,512,8), 256, wsmem>>>(fm, km1, bm1, t1);
    // 6. mpn conv2 (wmma tf32, inline weights): 64->64 -> m (raw logits)
    conv_wmma64_kernel<false><<<dim3(4,512,8), 256, wsmem>>>(t1, km2, bm2, mbuf);

    // 7. sigmoid + cumprod compositing -> fuse [H,W,K]
    composite_kernel<<<(unsigned)((KHW + 255)/256), 256>>>();

    // 8. un conv1: 8->32, relu (SIMT, R1 config)
    conv3x3_kernel<8,32,8,16,16,4,2,true><<<dim3(32,32,1), 128>>>(fuse, ku1, bu1, u1, 32, 0);
    // 9. un conv2: 32->3 -> output (SIMT, R1 config)
    conv3x3_kernel<32,3,16,16,16,4,1,false><<<dim3(32,32,1), 64>>>(u1, ku2, bu2, out, 3, 0);

    (void)in_sizes; (void)n_in; (void)out_size;
}

// round 13
// speedup vs baseline: 1.4652x; 1.0722x over previous
#include <cuda_runtime.h>
#include <math.h>
#include <stdint.h>
#include <mma.h>

using namespace nvcuda;

#define Hdim 512
#define Wdim 512
#define Kdim 8
#define HW   (Hdim*Wdim)          // 262144
#define KHW  ((size_t)Kdim*HW)    // 2097152

// ---------------- scratch (device globals; no runtime allocation) ----------
__device__ float g_fm  [KHW*64];   // [K,H,W,64] : ch 0..31 = MLP feat, 32..63 = color feat
__device__ float g_t1  [KHW*64];   // mpn1 output
__device__ float g_m   [KHW*64];   // mpn2 raw logits
__device__ float g_ck  [KHW*3];    // colors transposed [K,H,W,3]
__device__ float g_tmp [KHW*32];   // sup1 output
__device__ float g_fuse[HW*Kdim];  // [H,W,K]
__device__ float g_u1  [HW*32];    // un1 output
__device__ float g_W2t [128*128];  // W2 transposed + tf32-rounded (col-major B)
__device__ float g_W3t [128*128];  // W3 rows 0..127 transposed + tf32-rounded

// ======================= helpers ===========================================
__device__ __forceinline__ uint32_t cvt_tf32(float f){
    uint32_t u; asm("cvt.rna.tf32.f32 %0, %1;" : "=r"(u) : "f"(f)); return u;
}
__device__ __forceinline__ float tf32r(float f){ return __uint_as_float(cvt_tf32(f)); }

// ---------------- MLP weight transpose + round: [128][128] -> [n][k] --------
__global__ void prep_mlp_wt(const float* __restrict__ w, float* __restrict__ wt){
    int i = blockIdx.x*256 + threadIdx.x;
    if (i >= 16384) return;
    int n = i & 127, k = i >> 7;
    wt[n*128 + k] = tf32r(w[k*128 + n]);
}

// ---------------- colors [H,W,3K] -> [K,H,W,3] ------------------------------
__global__ void transpose_colors_kernel(const float* __restrict__ colors) {
    size_t i = (size_t)blockIdx.x * blockDim.x + threadIdx.x;
    if (i >= KHW * 3) return;
    int c   = (int)(i % 3);
    size_t r = i / 3;
    int k   = (int)(r >> 18);
    int pix = (int)(r & (HW - 1));
    g_ck[i] = colors[(size_t)pix * (3*Kdim) + k*3 + c];
}

// ---------------- fused MLP: 3 ->128 ->128 ->(+3)->128 ->32 -----------------
// 64 points/CTA, 128 threads. L1/L4 SIMT fp32; L2/L3 wmma tf32 (A smem LDA=136,
// B col-major from prepped transposed weights). dirs rows + biases in fp32.
#define MLP_LDA 136
__global__ void __launch_bounds__(128) mlp_kernel(
    const float* __restrict__ ray,  const float* __restrict__ zbufs,
    const float* __restrict__ W1,   const float* __restrict__ b1,
    const float* __restrict__ W2t,  const float* __restrict__ b2,
    const float* __restrict__ W3t,  const float* __restrict__ W3raw,
    const float* __restrict__ b3,
    const float* __restrict__ W4,   const float* __restrict__ b4)
{
    extern __shared__ float sh[];
    float* hA    = sh;                      // 64*136
    float* hB    = sh + 64*MLP_LDA;         // 64*136
    float* s_xyz = sh + 2*64*MLP_LDA;       // 64*3
    float* s_dir = s_xyz + 192;             // 64*3
    float* s_msk = s_dir + 192;             // 64
    const int tid = threadIdx.x;
    const int wid = tid >> 5;
    const size_t pt0 = (size_t)blockIdx.x * 64;

    if (tid < 64) {
        size_t pt = pt0 + tid;
        int k = (int)(pt >> 18);
        int r = (int)(pt & (HW - 1));
        const float* rp = ray + (size_t)r * 7;
        float z = zbufs[(size_t)r * Kdim + k];
        float t = z / rp[6];
        s_xyz[tid*3+0] = rp[0] + rp[3]*t;
        s_xyz[tid*3+1] = rp[1] + rp[4]*t;
        s_xyz[tid*3+2] = rp[2] + rp[5]*t;
        s_dir[tid*3+0] = rp[3];
        s_dir[tid*3+1] = rp[4];
        s_dir[tid*3+2] = rp[5];
        s_msk[tid] = (z > 0.0f) ? 1.0f : 0.0f;
    }
    __syncthreads();

    // ---- layer 1 (SIMT): 3 -> 128, relu, round to tf32 for L2's A operand
    {
        float w0 = W1[tid], w1 = W1[128+tid], w2 = W1[256+tid], b = b1[tid];
        for (int p = 0; p < 64; p++) {
            float v = b + s_xyz[p*3]*w0 + s_xyz[p*3+1]*w1 + s_xyz[p*3+2]*w2;
            hA[p*MLP_LDA + tid] = tf32r(fmaxf(v, 0.0f));
        }
    }
    __syncthreads();

    const int wm = wid & 1;   // 2 m-tiles of 32 points
    const int wn = wid >> 1;  // 2 n-tiles of 64 cols

    // ---- layer 2 (wmma tf32): 128 -> 128, hA -> hB
    {
        wmma::fragment<wmma::accumulator, 16, 16, 8, float> acc[2][4];
        #pragma unroll
        for (int mt = 0; mt < 2; mt++)
            #pragma unroll
            for (int nt = 0; nt < 4; nt++) wmma::fill_fragment(acc[mt][nt], 0.0f);
        for (int k0 = 0; k0 < 128; k0 += 8) {
            wmma::fragment<wmma::matrix_a, 16, 16, 8, wmma::precision::tf32, wmma::row_major> af[2];
            #pragma unroll
            for (int mt = 0; mt < 2; mt++)
                wmma::load_matrix_sync(af[mt], &hA[(wm*32 + mt*16)*MLP_LDA + k0], MLP_LDA);
            #pragma unroll
            for (int nt = 0; nt < 4; nt++) {
                wmma::fragment<wmma::matrix_b, 16, 16, 8, wmma::precision::tf32, wmma::col_major> bf;
                wmma::load_matrix_sync(bf, W2t + (wn*64 + nt*16)*128 + k0, 128);
                #pragma unroll
                for (int mt = 0; mt < 2; mt++)
                    wmma::mma_sync(acc[mt][nt], af[mt], bf, acc[mt][nt]);
            }
        }
        #pragma unroll
        for (int mt = 0; mt < 2; mt++)
            #pragma unroll
            for (int nt = 0; nt < 4; nt++)
                wmma::store_matrix_sync(&hB[(wm*32 + mt*16)*MLP_LDA + wn*64 + nt*16],
                                        acc[mt][nt], MLP_LDA, wmma::mem_row_major);
    }
    __syncthreads();
    for (int i = tid; i < 64*128; i += 128) {
        int p = i >> 7, c = i & 127;
        hB[p*MLP_LDA + c] = tf32r(fmaxf(hB[p*MLP_LDA + c] + b2[c], 0.0f));
    }
    __syncthreads();

    // ---- layer 3 (wmma tf32): first 128 rows via mma, dirs rows in fp32
    {
        wmma::fragment<wmma::accumulator, 16, 16, 8, float> acc[2][4];
        #pragma unroll
        for (int mt = 0; mt < 2; mt++)
            #pragma unroll
            for (int nt = 0; nt < 4; nt++) wmma::fill_fragment(acc[mt][nt], 0.0f);
        for (int k0 = 0; k0 < 128; k0 += 8) {
            wmma::fragment<wmma::matrix_a, 16, 16, 8, wmma::precision::tf32, wmma::row_major> af[2];
            #pragma unroll
            for (int mt = 0; mt < 2; mt++)
                wmma::load_matrix_sync(af[mt], &hB[(wm*32 + mt*16)*MLP_LDA + k0], MLP_LDA);
            #pragma unroll
            for (int nt = 0; nt < 4; nt++) {
                wmma::fragment<wmma::matrix_b, 16, 16, 8, wmma::precision::tf32, wmma::col_major> bf;
                wmma::load_matrix_sync(bf, W3t + (wn*64 + nt*16)*128 + k0, 128);
                #pragma unroll
                for (int mt = 0; mt < 2; mt++)
                    wmma::mma_sync(acc[mt][nt], af[mt], bf, acc[mt][nt]);
            }
        }
        #pragma unroll
        for (int mt = 0; mt < 2; mt++)
            #pragma unroll
            for (int nt = 0; nt < 4; nt++)
                wmma::store_matrix_sync(&hA[(wm*32 + mt*16)*MLP_LDA + wn*64 + nt*16],
                                        acc[mt][nt], MLP_LDA, wmma::mem_row_major);
    }
    __syncthreads();
    for (int i = tid; i < 64*128; i += 128) {
        int p = i >> 7, c = i & 127;
        float v = hA[p*MLP_LDA + c] + b3[c]
                + s_dir[p*3+0]*W3raw[128*128 + c]
                + s_dir[p*3+1]*W3raw[129*128 + c]
                + s_dir[p*3+2]*W3raw[130*128 + c];
        hA[p*MLP_LDA + c] = fmaxf(v, 0.0f);
    }
    __syncthreads();

    // ---- layer 4 (SIMT): 128 -> 32, mask, write fm channels 0..31
    {
        const int od = tid & 31;
        const int pg = tid >> 5;
        float acc[16];
        #pragma unroll
        for (int u = 0; u < 16; u++) acc[u] = b4[od];
        for (int c = 0; c < 128; c += 4) {
            float w0 = W4[c*32+od], w1 = W4[(c+1)*32+od];
            float w2 = W4[(c+2)*32+od], w3 = W4[(c+3)*32+od];
            #pragma unroll
            for (int u = 0; u < 16; u++) {
                float4 v = *(const float4*)&hA[(pg*16+u)*MLP_LDA + c];
                acc[u] += v.x*w0 + v.y*w1 + v.z*w2 + v.w*w3;
            }
        }
        #pragma unroll
        for (int u = 0; u < 16; u++) {
            int p = pg*16 + u;
            g_fm[(pt0 + p)*64 + od] = acc[u] * s_msk[p];
        }
    }
}

// ---------------- generic fused-tile 3x3 SAME conv (SIMT) -------------------
template<int CIN, int COUT, int CHK, int TH, int TW, int PPT, int CG, bool RELU>
__global__ void __launch_bounds__((TH*TW/PPT)*CG) conv3x3_kernel(
    const float* __restrict__ in, const float* __restrict__ wt,
    const float* __restrict__ bias, float* __restrict__ out,
    int ostride, int ooffs)
{
    constexpr int CPT = COUT / CG;
    constexpr int NT  = (TH*TW/PPT)*CG;
    __shared__ float s_in[TH+2][TW+2][CHK+1];
    __shared__ float s_wt[9][CHK][COUT];

    const int tid = threadIdx.x;
    const int n   = blockIdx.z;
    const int by  = blockIdx.y * TH;
    const int bx  = blockIdx.x * TW;
    const int cg  = tid % CG;
    const int pg  = tid / CG;
    const int p0  = pg * PPT;
    const int py  = p0 / TW;
    const int px0 = p0 % TW;

    float acc[PPT][CPT];
    #pragma unroll
    for (int u = 0; u < PPT; u++)
        #pragma unroll
        for (int u2 = 0; u2 < CPT; u2++) acc[u][u2] = bias[cg*CPT + u2];

    for (int c0 = 0; c0 < CIN; c0 += CHK) {
        for (int i = tid; i < (TH+2)*(TW+2)*CHK; i += NT) {
            int ci = i % CHK;
            int xy = i / CHK;
            int xx = xy % (TW+2);
            int yy = xy / (TW+2);
            int gy = by + yy - 1, gx = bx + xx - 1;
            float v = 0.0f;
            if (gy >= 0 && gy < Hdim && gx >= 0 && gx < Wdim)
                v = in[(((size_t)n*Hdim + gy)*Wdim + gx)*CIN + c0 + ci];
            s_in[yy][xx][ci] = v;
        }
        for (int i = tid; i < 9*CHK*COUT; i += NT) {
            int co = i % COUT;
            int rc = i / COUT;
            int ci = rc % CHK;
            int tap = rc / CHK;
            s_wt[tap][ci][co] = wt[((size_t)tap*CIN + c0 + ci)*COUT + co];
        }
        __syncthreads();

        for (int tap = 0; tap < 9; tap++) {
            int ky = tap / 3, kx = tap % 3;
            #pragma unroll
            for (int ci = 0; ci < CHK; ci++) {
                float wv[CPT];
                #pragma unroll
                for (int u2 = 0; u2 < CPT; u2++) wv[u2] = s_wt[tap][ci][cg*CPT + u2];
                #pragma unroll
                for (int u = 0; u < PPT; u++) {
                    float v = s_in[py+ky][px0+u+kx][ci];
                    #pragma unroll
                    for (int u2 = 0; u2 < CPT; u2++) acc[u][u2] += v * wv[u2];
                }
            }
        }
        __syncthreads();
    }

    #pragma unroll
    for (int u = 0; u < PPT; u++) {
        int gy = by + py, gx = bx + px0 + u;
        size_t ob = (((size_t)n*Hdim + gy)*Wdim + gx)*(size_t)ostride + ooffs + cg*CPT;
        #pragma unroll
        for (int u2 = 0; u2 < CPT; u2++)
            out[ob + u2] = RELU ? fmaxf(acc[u][u2], 0.0f) : acc[u][u2];
    }
}

// ======================= wmma tf32 conv3x3 (generic CIN/COUT) ================
// CTA: 128-px W strip, all COUT. Warp grid: WN=COUT/32 cols, WM=8/WN rows,
// MT=128/(WM*16) m-frags x 2 n-frags. A staged per input row (LDA=CIN+8; row
// stride multiple of 32B). B staged per-ky from HWIO weights (tf32-rounded)
// into [kl=kx*C8+c8][co][kloc] col-major chunks. D staged over region 0.
template<int CIN, int COUT, int OSTRIDE, int OCH, bool RELU>
__global__ void __launch_bounds__(256) conv_wmma_kernel(
    const float* __restrict__ in,   // [K,H,W,CIN]
    const float* __restrict__ wt,   // [3,3,CIN,COUT] HWIO (fp32)
    const float* __restrict__ bias, // [COUT]
    float* __restrict__ out)
{
    constexpr int C8  = CIN/8;
    constexpr int LDA = CIN + 8;
    constexpr int B_CHUNK  = 3*C8*COUT*8;
    constexpr int D_REGION = (B_CHUNK > 128*COUT) ? B_CHUNK : 128*COUT;
    constexpr int WN = COUT/32;
    constexpr int WM = 8/WN;
    constexpr int MT = 128/(WM*16);
    extern __shared__ float smem[];
    float* sB = smem;                 // B_CHUNK (D staging uses D_REGION)
    float* sA = smem + D_REGION;      // 130*LDA floats

    const int tid = threadIdx.x, wid = tid >> 5;
    const int wm = wid % WM, wn = wid / WM;
    const int kimg = blockIdx.z, y = blockIdx.y, x0 = blockIdx.x * 128;

    wmma::fragment<wmma::accumulator, 16, 16, 8, float> acc[MT][2];
    #pragma unroll
    for (int mt = 0; mt < MT; mt++)
        #pragma unroll
        for (int nt = 0; nt < 2; nt++)
            wmma::fill_fragment(acc[mt][nt], 0.0f);

    for (int ky = 0; ky < 3; ky++) {
        __syncthreads();
        int gy = y + ky - 1;
        for (int i = tid; i < 130*(CIN/4); i += 256) {
            int c4 = i % (CIN/4);
            int px = i / (CIN/4);
            int gx = x0 + px - 1;
            float4 v = make_float4(0.f, 0.f, 0.f, 0.f);
            if (gy >= 0 && gy < Hdim && (unsigned)gx < (unsigned)Wdim)
                v = *(const float4*)(in + (((size_t)(kimg*Hdim + gy))*Wdim + gx)*CIN + c4*4);
            float4 r = make_float4(tf32r(v.x), tf32r(v.y), tf32r(v.z), tf32r(v.w));
            *(float4*)&sA[px*LDA + c4*4] = r;
        }
        for (int i = tid; i < B_CHUNK; i += 256) {
            int co   = i % COUT;
            int r    = i / COUT;
            int kloc = r & 7;
            int kl   = r >> 3;          // 0..3*C8-1 = kx*C8 + c8
            int kx   = kl / C8;
            int c8   = kl % C8;
            int ci   = c8*8 + kloc;
            float w = wt[((size_t)(ky*3 + kx)*CIN + ci)*COUT + co];
            sB[((kl*COUT) + co)*8 + kloc] = tf32r(w);
        }
        __syncthreads();

        for (int kx = 0; kx < 3; kx++) {
            #pragma unroll
            for (int c8 = 0; c8 < C8; c8++) {
                int kl = kx*C8 + c8;
                wmma::fragment<wmma::matrix_a, 16, 16, 8, wmma::precision::tf32, wmma::row_major> af[MT];
                #pragma unroll
                for (int mt = 0; mt < MT; mt++)
                    wmma::load_matrix_sync(af[mt], &sA[(wm*MT*16 + mt*16 + kx)*LDA + c8*8], LDA);
                #pragma unroll
                for (int nt = 0; nt < 2; nt++) {
                    wmma::fragment<wmma::matrix_b, 16, 16, 8, wmma::precision::tf32, wmma::col_major> bf;
                    wmma::load_matrix_sync(bf, &sB[(kl*COUT + wn*32 + nt*16)*8], 8);
                    #pragma unroll
                    for (int mt = 0; mt < MT; mt++)
                        wmma::mma_sync(acc[mt][nt], af[mt], bf, acc[mt][nt]);
                }
            }
        }
    }

    __syncthreads();
    #pragma unroll
    for (int mt = 0; mt < MT; mt++)
        #pragma unroll
        for (int nt = 0; nt < 2; nt++)
            wmma::store_matrix_sync(&sB[(wm*MT*16 + mt*16)*COUT + wn*32 + nt*16],
                                    acc[mt][nt], COUT, wmma::mem_row_major);
    __syncthreads();

    for (int i = tid; i < 128*(COUT/4); i += 256) {
        int c4 = i % (COUT/4);
        int px = i / (COUT/4);
        float4 v = *(float4*)&sB[px*COUT + c4*4];
        v.x += bias[c4*4+0]; v.y += bias[c4*4+1];
        v.z += bias[c4*4+2]; v.w += bias[c4*4+3];
        if (RELU) {
            v.x = fmaxf(v.x, 0.f); v.y = fmaxf(v.y, 0.f);
            v.z = fmaxf(v.z, 0.f); v.w = fmaxf(v.w, 0.f);
        }
        *(float4*)(out + (((size_t)(kimg*Hdim + y))*Wdim + (x0 + px))*OSTRIDE + OCH + c4*4) = v;
    }
}

// ---------------- sigmoid + cumprod alpha compositing ------------------------
__global__ void composite_kernel() {
    size_t pt = (size_t)blockIdx.x * blockDim.x + threadIdx.x;
    if (pt >= KHW) return;
    const float4* f4 = (const float4*)(g_fm + pt*64);
    const float4* m4 = (const float4*)(g_m  + pt*64);
    float alpha = 1.0f, acc = 0.0f;
    #pragma unroll 4
    for (int i = 0; i < 16; i++) {
        float4 f = f4[i], mr = m4[i];
        float m;
        m = 1.0f/(1.0f+expf(-mr.x)); acc += f.x*m*alpha; alpha *= (1.0f-m);
        m = 1.0f/(1.0f+expf(-mr.y)); acc += f.y*m*alpha; alpha *= (1.0f-m);
        m = 1.0f/(1.0f+expf(-mr.z)); acc += f.z*m*alpha; alpha *= (1.0f-m);
        m = 1.0f/(1.0f+expf(-mr.w)); acc += f.w*m*alpha; alpha *= (1.0f-m);
    }
    int k = (int)(pt >> 18);
    int pix = (int)(pt & (HW - 1));
    g_fuse[(size_t)pix*Kdim + k] = acc;   // [H,W,K]
}

// ---------------- launch orchestration ---------------------------------------
extern "C" void kernel_launch(void* const* d_in, const int* in_sizes, int n_in,
                              void* d_out, int out_size)
{
    const float* colors = (const float*)d_in[0];
    const float* ray    = (const float*)d_in[1];
    const float* zbufs  = (const float*)d_in[2];
    const float* W1 = (const float*)d_in[3];   const float* b1 = (const float*)d_in[4];
    const float* W2 = (const float*)d_in[5];   const float* b2 = (const float*)d_in[6];
    const float* W3 = (const float*)d_in[7];   const float* b3 = (const float*)d_in[8];
    const float* W4 = (const float*)d_in[9];   const float* b4 = (const float*)d_in[10];
    const float* ks1 = (const float*)d_in[11]; const float* bs1 = (const float*)d_in[12];
    const float* ks2 = (const float*)d_in[13]; const float* bs2 = (const float*)d_in[14];
    const float* km1 = (const float*)d_in[15]; const float* bm1 = (const float*)d_in[16];
    const float* km2 = (const float*)d_in[17]; const float* bm2 = (const float*)d_in[18];
    const float* ku1 = (const float*)d_in[19]; const float* bu1 = (const float*)d_in[20];
    const float* ku2 = (const float*)d_in[21]; const float* bu2 = (const float*)d_in[22];
    float* out = (float*)d_out;

    float *fm, *t1, *mbuf, *ck, *fuse, *u1, *tmp, *w2t, *w3t;
    cudaGetSymbolAddress((void**)&fm,   g_fm);
    cudaGetSymbolAddress((void**)&t1,   g_t1);
    cudaGetSymbolAddress((void**)&mbuf, g_m);
    cudaGetSymbolAddress((void**)&ck,   g_ck);
    cudaGetSymbolAddress((void**)&fuse, g_fuse);
    cudaGetSymbolAddress((void**)&u1,   g_u1);
    cudaGetSymbolAddress((void**)&tmp,  g_tmp);
    cudaGetSymbolAddress((void**)&w2t,  g_W2t);
    cudaGetSymbolAddress((void**)&w3t,  g_W3t);

    const int mlp_smem = (2*64*MLP_LDA + 64*3*2 + 64) * (int)sizeof(float);  // ~71.4 KB
    cudaFuncSetAttribute(mlp_kernel, cudaFuncAttributeMaxDynamicSharedMemorySize, mlp_smem);

    const int wsmem64 = (3*8*64*8 + 130*72) * (int)sizeof(float);            // 86592
    const int wsmem32 = (128*32 + 130*40) * (int)sizeof(float);              // 37184
    cudaFuncSetAttribute(conv_wmma_kernel<64,64,64,0,true>,
                         cudaFuncAttributeMaxDynamicSharedMemorySize, wsmem64);
    cudaFuncSetAttribute(conv_wmma_kernel<64,64,64,0,false>,
                         cudaFuncAttributeMaxDynamicSharedMemorySize, wsmem64);
    cudaFuncSetAttribute(conv_wmma_kernel<32,32,64,32,false>,
                         cudaFuncAttributeMaxDynamicSharedMemorySize, wsmem32);

    // 0. MLP weight transpose + tf32 round
    prep_mlp_wt<<<64, 256>>>(W2, w2t);
    prep_mlp_wt<<<64, 256>>>(W3, w3t);

    // 1. colors -> [K,H,W,3]
    transpose_colors_kernel<<<(unsigned)((KHW*3 + 255)/256), 256>>>(colors);

    // 2. radiance-mapping MLP (L2/L3 wmma tf32) -> fm ch 0..31 (masked)
    mlp_kernel<<<(unsigned)(KHW/64), 128, mlp_smem>>>(
        ray, zbufs, W1, b1, w2t, b2, w3t, W3, b3, W4, b4);

    // 3. sup conv1: 3->32, relu -> tmp (SIMT)
    conv3x3_kernel<3,32,3,16,16,4,2,true><<<dim3(32,32,8), 128>>>(ck, ks1, bs1, tmp, 32, 0);
    // 4. sup conv2 (wmma tf32): 32->32 -> fm ch 32..63
    conv_wmma_kernel<32,32,64,32,false><<<dim3(4,512,8), 256, wsmem32>>>(tmp, ks2, bs2, fm);

    // 5. mpn conv1 (wmma tf32): 64->64, relu -> t1
    conv_wmma_kernel<64,64,64,0,true><<<dim3(4,512,8), 256, wsmem64>>>(fm, km1, bm1, t1);
    // 6. mpn conv2 (wmma tf32): 64->64 -> m (raw logits)
    conv_wmma_kernel<64,64,64,0,false><<<dim3(4,512,8), 256, wsmem64>>>(t1, km2, bm2, mbuf);

    // 7. sigmoid + cumprod compositing -> fuse [H,W,K]
    composite_kernel<<<(unsigned)((KHW + 255)/256), 256>>>();

    // 8. un conv1: 8->32, relu (SIMT)
    conv3x3_kernel<8,32,8,16,16,4,2,true><<<dim3(32,32,1), 128>>>(fuse, ku1, bu1, u1, 32, 0);
    // 9. un conv2: 32->3 -> output (SIMT)
    conv3x3_kernel<32,3,16,16,16,4,1,false><<<dim3(32,32,1), 64>>>(u1, ku2, bu2, out, 3, 0);

    (void)in_sizes; (void)n_in; (void)out_size;
}